// round 1
// baseline (speedup 1.0000x reference)
#include <cuda_runtime.h>
#include <float.h>
#include <stdint.h>

#define N_NODES 100000
#define N_EDGES 1600000
#define D 128

// Scratch: aggregation buffer (51.2 MB), static __device__ per harness rules.
__device__ float g_agg[(size_t)N_NODES * D];

// ---------------------------------------------------------------------------
// Kernel 1: init agg to -FLT_MAX (sentinel == "no incoming edge yet")
// ---------------------------------------------------------------------------
__global__ void __launch_bounds__(256) init_agg_kernel() {
    size_t i = (size_t)blockIdx.x * blockDim.x + threadIdx.x;
    const size_t n4 = (size_t)N_NODES * D / 4;
    if (i < n4) {
        float4 v = make_float4(-FLT_MAX, -FLT_MAX, -FLT_MAX, -FLT_MAX);
        reinterpret_cast<float4*>(g_agg)[i] = v;
    }
}

// float atomic-max via signed-int max / unsigned min (order-preserving maps)
__device__ __forceinline__ void atomicMaxF(float* addr, float v) {
    if (v >= 0.0f) atomicMax(reinterpret_cast<int*>(addr), __float_as_int(v));
    else atomicMin(reinterpret_cast<unsigned int*>(addr), __float_as_uint(v));
}

// ---------------------------------------------------------------------------
// Kernel 2: edge scatter-max. One warp per edge: 32 lanes x float4 = 128 feats.
// Racy read-filter: only atomic when the candidate currently wins (agg is
// monotonically increasing, so a stale read can only cause an extra atomic,
// never a missed one).
// ---------------------------------------------------------------------------
__global__ void __launch_bounds__(256) scatter_max_kernel(
    const float* __restrict__ H,
    const int*   __restrict__ src,
    const int*   __restrict__ dst)
{
    int e    = (int)((blockIdx.x * blockDim.x + threadIdx.x) >> 5);
    int lane = threadIdx.x & 31;
    if (e >= N_EDGES) return;

    int s = src[e];
    int d = dst[e];

    const float4* h4 = reinterpret_cast<const float4*>(H + (size_t)d * D);
    float4*       a4 = reinterpret_cast<float4*>(g_agg + (size_t)s * D);

    float4 h   = h4[lane];
    float4 cur = a4[lane];
    float* ap  = reinterpret_cast<float*>(a4 + lane);

    if (h.x > cur.x) atomicMaxF(ap + 0, h.x);
    if (h.y > cur.y) atomicMaxF(ap + 1, h.y);
    if (h.z > cur.z) atomicMaxF(ap + 2, h.z);
    if (h.w > cur.w) atomicMaxF(ap + 3, h.w);
}

// ---------------------------------------------------------------------------
// Kernel 3: fused finalize + GEMM.
//   out[m][o] = sum_{k<128} H[m][k]*W[o][k]
//            + sum_{k<128} fix(agg[m][k])*W[o][128+k]  + b[o]
// where fix(x) = (x == -FLT_MAX) ? 0 : x.
// Block tile: 64 rows x 128 cols, K chunks of 16. Packed fp32x2 FMA.
// ---------------------------------------------------------------------------
#define BM 64
#define BN 128
#define BK 16
#define KDIM 256
#define AS_STRIDE 20    // padded: bank-spread stores, broadcast reads
#define BS_STRIDE 130   // padded: conflict-free transpose stores, aligned f32x2 reads

#define FMA_F32X2(d, a, b, c) \
    asm("fma.rn.f32x2 %0, %1, %2, %3;" : "=l"(d) : "l"(a), "l"(b), "l"(c))

__device__ __forceinline__ unsigned long long dup_f32x2(float x) {
    unsigned long long r;
    asm("mov.b64 %0, {%1, %1};" : "=l"(r) : "f"(x));
    return r;
}

__global__ void __launch_bounds__(256) fused_gemm_kernel(
    const float* __restrict__ H,
    const float* __restrict__ W,     // [128][256] row-major
    const float* __restrict__ bias,  // [128]
    float* __restrict__ out)         // [N_NODES][128]
{
    __shared__ float As[BM * AS_STRIDE];
    __shared__ float Bs[BK * BS_STRIDE];

    const int tid = threadIdx.x;
    const int tx  = tid & 31;   // output column group: cols [tx*4, tx*4+4)
    const int ty  = tid >> 5;   // row group: rows [ty*8, ty*8+8)
    const int m0  = blockIdx.x * BM;

    unsigned long long acc[8][2];
#pragma unroll
    for (int i = 0; i < 8; i++) { acc[i][0] = 0ULL; acc[i][1] = 0ULL; }

    // A-tile loader mapping: row am (0..63), quad aq (0..3) -> 4 consecutive k
    const int am = tid >> 2;
    const int aq = tid & 3;
    const int gm_a = m0 + am;

    // B-tile loader mapping: k index bj (0..15), column base obase (0..15)
    const int bj    = tid & 15;
    const int obase = tid >> 4;

    for (int kc = 0; kc < KDIM; kc += BK) {
        // ---- load A tile (concat input, with -FLT_MAX -> 0 fix) ----
        float4 av = make_float4(0.f, 0.f, 0.f, 0.f);
        if (gm_a < N_NODES) {
            int k = kc + aq * 4;
            if (k < 128) {
                av = *reinterpret_cast<const float4*>(H + (size_t)gm_a * D + k);
            } else {
                av = *reinterpret_cast<const float4*>(g_agg + (size_t)gm_a * D + (k - 128));
                if (av.x == -FLT_MAX) av.x = 0.f;
                if (av.y == -FLT_MAX) av.y = 0.f;
                if (av.z == -FLT_MAX) av.z = 0.f;
                if (av.w == -FLT_MAX) av.w = 0.f;
            }
        }
        *reinterpret_cast<float4*>(&As[am * AS_STRIDE + aq * 4]) = av;

        // ---- load + transpose B tile: Bs[k][o] = W[o][kc+k] ----
#pragma unroll
        for (int it = 0; it < 8; it++) {
            int o = obase + it * 16;
            Bs[bj * BS_STRIDE + o] = W[o * KDIM + kc + bj];
        }
        __syncthreads();

        // ---- compute ----
#pragma unroll
        for (int k = 0; k < BK; k++) {
            unsigned long long b0 =
                *reinterpret_cast<const unsigned long long*>(&Bs[k * BS_STRIDE + tx * 4]);
            unsigned long long b1 =
                *reinterpret_cast<const unsigned long long*>(&Bs[k * BS_STRIDE + tx * 4 + 2]);
#pragma unroll
            for (int i = 0; i < 8; i++) {
                unsigned long long a2 = dup_f32x2(As[(ty * 8 + i) * AS_STRIDE + k]);
                FMA_F32X2(acc[i][0], a2, b0, acc[i][0]);
                FMA_F32X2(acc[i][1], a2, b1, acc[i][1]);
            }
        }
        __syncthreads();
    }

    // ---- epilogue: add bias, store ----
    float4 bv = *reinterpret_cast<const float4*>(bias + tx * 4);
#pragma unroll
    for (int i = 0; i < 8; i++) {
        int gm = m0 + ty * 8 + i;
        if (gm < N_NODES) {
            float2 lo, hi;
            asm("mov.b64 {%0, %1}, %2;" : "=f"(lo.x), "=f"(lo.y) : "l"(acc[i][0]));
            asm("mov.b64 {%0, %1}, %2;" : "=f"(hi.x), "=f"(hi.y) : "l"(acc[i][1]));
            float4 ov = make_float4(lo.x + bv.x, lo.y + bv.y, hi.x + bv.z, hi.y + bv.w);
            *reinterpret_cast<float4*>(out + (size_t)gm * D + tx * 4) = ov;
        }
    }
}

// ---------------------------------------------------------------------------
// Launch
// ---------------------------------------------------------------------------
extern "C" void kernel_launch(void* const* d_in, const int* in_sizes, int n_in,
                              void* d_out, int out_size) {
    const float* H   = (const float*)d_in[0];
    const int*   src = (const int*)d_in[1];
    const int*   dst = (const int*)d_in[2];
    const float* W   = (const float*)d_in[3];
    const float* b   = (const float*)d_in[4];
    float*       out = (float*)d_out;

    const int init_elems = N_NODES * D / 4;
    init_agg_kernel<<<(init_elems + 255) / 256, 256>>>();

    const long long scatter_threads = (long long)N_EDGES * 32;
    scatter_max_kernel<<<(unsigned)((scatter_threads + 255) / 256), 256>>>(H, src, dst);

    fused_gemm_kernel<<<(N_NODES + BM - 1) / BM, 256>>>(H, W, b, out);
}

// round 3
// speedup vs baseline: 2.3886x; 2.3886x over previous
#include <cuda_runtime.h>
#include <cuda_bf16.h>
#include <float.h>
#include <stdint.h>

#define N_NODES 100000
#define N_EDGES 1600000
#define D 128
#define KDIM 256

// ---------------------------------------------------------------------------
// Device scratch (static per harness rules)
// ---------------------------------------------------------------------------
__device__ float g_agg[(size_t)N_NODES * D];
__device__ int   g_deg[N_NODES];
__device__ int   g_off[N_NODES];
__device__ int   g_cur[N_NODES];
__device__ int   g_adj[N_EDGES];
__device__ int   g_bsum[128];
__device__ int   g_bsumoff[128];
__device__ __align__(16) __nv_bfloat16 g_Wh[128 * KDIM];  // W split hi
__device__ __align__(16) __nv_bfloat16 g_Wl[128 * KDIM];  // W split lo

// ===========================================================================
// CSR build
// ===========================================================================
__global__ void __launch_bounds__(256) zero_csr_kernel() {
    int i = blockIdx.x * blockDim.x + threadIdx.x;
    if (i < N_NODES) { g_deg[i] = 0; g_cur[i] = 0; }
}

__global__ void __launch_bounds__(256) hist_kernel(const int* __restrict__ src) {
    int e = blockIdx.x * blockDim.x + threadIdx.x;
    if (e < N_EDGES) atomicAdd(&g_deg[src[e]], 1);
}

__global__ void __launch_bounds__(1024) scan_partial_kernel() {
    __shared__ int s[1024];
    int i = blockIdx.x * 1024 + threadIdx.x;
    int v = (i < N_NODES) ? g_deg[i] : 0;
    s[threadIdx.x] = v;
    __syncthreads();
#pragma unroll
    for (int ofs = 1; ofs < 1024; ofs <<= 1) {
        int t = (threadIdx.x >= ofs) ? s[threadIdx.x - ofs] : 0;
        __syncthreads();
        s[threadIdx.x] += t;
        __syncthreads();
    }
    if (i < N_NODES) g_off[i] = s[threadIdx.x] - v;
    if (threadIdx.x == 1023) g_bsum[blockIdx.x] = s[1023];
}

__global__ void __launch_bounds__(128) scan_bsums_kernel(int nblocks) {
    __shared__ int s[128];
    int v = (threadIdx.x < nblocks) ? g_bsum[threadIdx.x] : 0;
    s[threadIdx.x] = v;
    __syncthreads();
#pragma unroll
    for (int ofs = 1; ofs < 128; ofs <<= 1) {
        int t = (threadIdx.x >= ofs) ? s[threadIdx.x - ofs] : 0;
        __syncthreads();
        s[threadIdx.x] += t;
        __syncthreads();
    }
    g_bsumoff[threadIdx.x] = s[threadIdx.x] - v;
}

__global__ void __launch_bounds__(256) scan_add_kernel() {
    int i = blockIdx.x * blockDim.x + threadIdx.x;
    if (i < N_NODES) g_off[i] += g_bsumoff[i >> 10];
}

__global__ void __launch_bounds__(256) fill_adj_kernel(const int* __restrict__ src,
                                                       const int* __restrict__ dst) {
    int e = blockIdx.x * blockDim.x + threadIdx.x;
    if (e < N_EDGES) {
        int s = src[e];
        int pos = g_off[s] + atomicAdd(&g_cur[s], 1);
        g_adj[pos] = dst[e];
    }
}

// ===========================================================================
// Aggregate: one warp per node, gather-max over CSR neighbors. No atomics.
// ===========================================================================
__device__ __forceinline__ float4 max4(float4 a, float4 b) {
    return make_float4(fmaxf(a.x, b.x), fmaxf(a.y, b.y),
                       fmaxf(a.z, b.z), fmaxf(a.w, b.w));
}

__global__ void __launch_bounds__(256) aggregate_kernel(const float* __restrict__ H) {
    int node = (int)((blockIdx.x * blockDim.x + threadIdx.x) >> 5);
    int lane = threadIdx.x & 31;
    if (node >= N_NODES) return;

    int off = g_off[node];
    int deg = g_deg[node];

    float4 m = make_float4(-FLT_MAX, -FLT_MAX, -FLT_MAX, -FLT_MAX);
    int j = 0;
    for (; j + 4 <= deg; j += 4) {
        int n0 = g_adj[off + j + 0];
        int n1 = g_adj[off + j + 1];
        int n2 = g_adj[off + j + 2];
        int n3 = g_adj[off + j + 3];
        float4 v0 = *reinterpret_cast<const float4*>(H + (size_t)n0 * D + lane * 4);
        float4 v1 = *reinterpret_cast<const float4*>(H + (size_t)n1 * D + lane * 4);
        float4 v2 = *reinterpret_cast<const float4*>(H + (size_t)n2 * D + lane * 4);
        float4 v3 = *reinterpret_cast<const float4*>(H + (size_t)n3 * D + lane * 4);
        m = max4(m, max4(max4(v0, v1), max4(v2, v3)));
    }
    for (; j < deg; j++) {
        int n0 = g_adj[off + j];
        float4 v0 = *reinterpret_cast<const float4*>(H + (size_t)n0 * D + lane * 4);
        m = max4(m, v0);
    }
    if (deg == 0) m = make_float4(0.f, 0.f, 0.f, 0.f);
    *reinterpret_cast<float4*>(g_agg + (size_t)node * D + lane * 4) = m;
}

// ===========================================================================
// W hi/lo bf16 split (done once; tiny)
// ===========================================================================
__global__ void __launch_bounds__(256) wsplit_kernel(const float* __restrict__ W) {
    int i = blockIdx.x * blockDim.x + threadIdx.x;
    if (i < 128 * KDIM) {
        float v = W[i];
        __nv_bfloat16 h = __float2bfloat16_rn(v);
        g_Wh[i] = h;
        g_Wl[i] = __float2bfloat16_rn(v - __bfloat162float(h));
    }
}

// ===========================================================================
// GEMM: out[m][n] = sum_k [H|agg][m][k] * W[n][k] + b[n]
// mma.sync m16n8k16 bf16, 3-pass hi/lo split, fp32 accumulate.
// CTA 256 thr: tile M=128, N=128. Warp tile 32x64. K chunks of 32.
// ===========================================================================
__device__ __forceinline__ uint32_t smem_u32(const void* p) {
    uint32_t a;
    asm("{ .reg .u64 t; cvta.to.shared.u64 t, %1; cvt.u32.u64 %0, t; }"
        : "=r"(a) : "l"(p));
    return a;
}

__device__ __forceinline__ uint32_t sw64(uint32_t b) { return b ^ ((b >> 3) & 0x30); }

__device__ __forceinline__ void ldsm_x4(uint32_t& r0, uint32_t& r1, uint32_t& r2,
                                        uint32_t& r3, uint32_t addr) {
    asm volatile("ldmatrix.sync.aligned.m8n8.x4.shared.b16 {%0,%1,%2,%3}, [%4];"
                 : "=r"(r0), "=r"(r1), "=r"(r2), "=r"(r3) : "r"(addr));
}

__device__ __forceinline__ void mma_bf16(float* c, uint32_t a0, uint32_t a1,
                                         uint32_t a2, uint32_t a3,
                                         uint32_t b0, uint32_t b1) {
    asm volatile(
        "mma.sync.aligned.m16n8k16.row.col.f32.bf16.bf16.f32 "
        "{%0,%1,%2,%3},{%4,%5,%6,%7},{%8,%9},{%0,%1,%2,%3};"
        : "+f"(c[0]), "+f"(c[1]), "+f"(c[2]), "+f"(c[3])
        : "r"(a0), "r"(a1), "r"(a2), "r"(a3), "r"(b0), "r"(b1));
}

#define KC 32

__global__ void __launch_bounds__(256) gemm_mma_kernel(
    const float* __restrict__ H,
    const float* __restrict__ bias,
    float* __restrict__ out)
{
    // 4 x 8KB SW64-swizzled tiles (rows of 64 bytes)
    __shared__ __align__(1024) uint8_t sAh[128 * 64];
    __shared__ __align__(1024) uint8_t sAl[128 * 64];
    __shared__ __align__(1024) uint8_t sBh[128 * 64];
    __shared__ __align__(1024) uint8_t sBl[128 * 64];

    const int tid    = threadIdx.x;
    const int wid    = tid >> 5;
    const int lane   = tid & 31;
    const int warp_m = wid >> 1;       // 0..3
    const int warp_n = wid & 1;        // 0..1
    const int mblk   = blockIdx.x * 128;

    const uint32_t bAh = smem_u32(sAh);
    const uint32_t bAl = smem_u32(sAl);
    const uint32_t bBh = smem_u32(sBh);
    const uint32_t bBl = smem_u32(sBl);

    const int lsub = lane >> 3;        // ldmatrix submatrix id
    const int lr   = lane & 7;         // row within submatrix

    float acc[2][8][4];
#pragma unroll
    for (int f = 0; f < 2; f++)
#pragma unroll
        for (int t = 0; t < 8; t++)
#pragma unroll
            for (int i = 0; i < 4; i++) acc[f][t][i] = 0.f;

    for (int c = 0; c < 8; c++) {
        const int kc = c * KC;

        // ---- stage A chunk: 128 rows x 32 k, fp32 -> bf16 hi/lo, swizzled ----
        {
            const float* srcb = (kc < 128) ? (H + kc) : (g_agg + (kc - 128));
#pragma unroll
            for (int i = 0; i < 4; i++) {
                int idx = i * 256 + tid;
                int m = idx >> 3, q = idx & 7;
                int gm = mblk + m;
                float4 v = make_float4(0.f, 0.f, 0.f, 0.f);
                if (gm < N_NODES)
                    v = *reinterpret_cast<const float4*>(srcb + (size_t)gm * D + q * 4);
                __nv_bfloat162 h01 = __float22bfloat162_rn(make_float2(v.x, v.y));
                __nv_bfloat162 h23 = __float22bfloat162_rn(make_float2(v.z, v.w));
                float2 lo01 = make_float2(v.x - __low2float(h01), v.y - __high2float(h01));
                float2 lo23 = make_float2(v.z - __low2float(h23), v.w - __high2float(h23));
                __nv_bfloat162 l01 = __float22bfloat162_rn(lo01);
                __nv_bfloat162 l23 = __float22bfloat162_rn(lo23);
                uint32_t b = (uint32_t)(m * 64 + q * 8);
                uint32_t sb = sw64(b);
                *reinterpret_cast<uint2*>(sAh + sb) =
                    make_uint2(*reinterpret_cast<uint32_t*>(&h01),
                               *reinterpret_cast<uint32_t*>(&h23));
                *reinterpret_cast<uint2*>(sAl + sb) =
                    make_uint2(*reinterpret_cast<uint32_t*>(&l01),
                               *reinterpret_cast<uint32_t*>(&l23));
            }
        }

        // ---- stage B chunk: copy bf16 W hi/lo [n][kc..kc+32), swizzled ----
        {
#pragma unroll
            for (int i = 0; i < 2; i++) {
                int idx = i * 256 + tid;
                int n = idx >> 2, u = idx & 3;
                size_t srcoff = (size_t)n * KDIM + kc;   // in bf16 elems
                uint32_t sb = sw64((uint32_t)(n * 64 + u * 16));
                *reinterpret_cast<uint4*>(sBh + sb) =
                    *reinterpret_cast<const uint4*>(
                        reinterpret_cast<const uint8_t*>(g_Wh) + srcoff * 2 + u * 16);
                *reinterpret_cast<uint4*>(sBl + sb) =
                    *reinterpret_cast<const uint4*>(
                        reinterpret_cast<const uint8_t*>(g_Wl) + srcoff * 2 + u * 16);
            }
        }
        __syncthreads();

        // ---- compute: 2 k-steps of 16 ----
#pragma unroll
        for (int ks = 0; ks < 2; ks++) {
            const int k0 = ks * 16;
            uint32_t Ah[2][4], Al[2][4];
#pragma unroll
            for (int f = 0; f < 2; f++) {
                int row = warp_m * 32 + f * 16 + (lsub & 1) * 8 + lr;
                int kb  = k0 + (lsub >> 1) * 8;
                uint32_t ofs = sw64((uint32_t)(row * 64 + kb * 2));
                ldsm_x4(Ah[f][0], Ah[f][1], Ah[f][2], Ah[f][3], bAh + ofs);
                ldsm_x4(Al[f][0], Al[f][1], Al[f][2], Al[f][3], bAl + ofs);
            }
#pragma unroll
            for (int np = 0; np < 4; np++) {
                int n  = warp_n * 64 + np * 16 + (lsub >> 1) * 8 + lr;
                int kb = k0 + (lsub & 1) * 8;
                uint32_t ofs = sw64((uint32_t)(n * 64 + kb * 2));
                uint32_t Bh[4], Bl[4];
                ldsm_x4(Bh[0], Bh[1], Bh[2], Bh[3], bBh + ofs);
                ldsm_x4(Bl[0], Bl[1], Bl[2], Bl[3], bBl + ofs);
#pragma unroll
                for (int f = 0; f < 2; f++) {
                    // pass hh
                    mma_bf16(acc[f][np * 2 + 0], Ah[f][0], Ah[f][1], Ah[f][2], Ah[f][3], Bh[0], Bh[1]);
                    mma_bf16(acc[f][np * 2 + 1], Ah[f][0], Ah[f][1], Ah[f][2], Ah[f][3], Bh[2], Bh[3]);
                    // pass hl
                    mma_bf16(acc[f][np * 2 + 0], Ah[f][0], Ah[f][1], Ah[f][2], Ah[f][3], Bl[0], Bl[1]);
                    mma_bf16(acc[f][np * 2 + 1], Ah[f][0], Ah[f][1], Ah[f][2], Ah[f][3], Bl[2], Bl[3]);
                    // pass lh
                    mma_bf16(acc[f][np * 2 + 0], Al[f][0], Al[f][1], Al[f][2], Al[f][3], Bh[0], Bh[1]);
                    mma_bf16(acc[f][np * 2 + 1], Al[f][0], Al[f][1], Al[f][2], Al[f][3], Bh[2], Bh[3]);
                }
            }
        }
        __syncthreads();
    }

    // ---- epilogue: add bias, store fp32 ----
    const int mbase = mblk + warp_m * 32 + (lane >> 2);
#pragma unroll
    for (int f = 0; f < 2; f++) {
        int row0 = mbase + f * 16;
        int row1 = row0 + 8;
#pragma unroll
        for (int t = 0; t < 8; t++) {
            int col = warp_n * 64 + t * 8 + (lane & 3) * 2;
            float2 bv = *reinterpret_cast<const float2*>(bias + col);
            if (row0 < N_NODES) {
                float2 o = make_float2(acc[f][t][0] + bv.x, acc[f][t][1] + bv.y);
                *reinterpret_cast<float2*>(out + (size_t)row0 * D + col) = o;
            }
            if (row1 < N_NODES) {
                float2 o = make_float2(acc[f][t][2] + bv.x, acc[f][t][3] + bv.y);
                *reinterpret_cast<float2*>(out + (size_t)row1 * D + col) = o;
            }
        }
    }
}

// ===========================================================================
// Launch
// ===========================================================================
extern "C" void kernel_launch(void* const* d_in, const int* in_sizes, int n_in,
                              void* d_out, int out_size) {
    const float* H   = (const float*)d_in[0];
    const int*   src = (const int*)d_in[1];
    const int*   dst = (const int*)d_in[2];
    const float* W   = (const float*)d_in[3];
    const float* b   = (const float*)d_in[4];
    float*       out = (float*)d_out;

    const int nb_nodes = (N_NODES + 255) / 256;
    const int nb_edges = (N_EDGES + 255) / 256;
    const int nb_scan  = (N_NODES + 1023) / 1024;   // 98

    zero_csr_kernel<<<nb_nodes, 256>>>();
    wsplit_kernel<<<(128 * KDIM + 255) / 256, 256>>>(W);
    hist_kernel<<<nb_edges, 256>>>(src);
    scan_partial_kernel<<<nb_scan, 1024>>>();
    scan_bsums_kernel<<<1, 128>>>(nb_scan);
    scan_add_kernel<<<nb_nodes, 256>>>();
    fill_adj_kernel<<<nb_edges, 256>>>(src, dst);

    aggregate_kernel<<<(N_NODES * 32 + 255) / 256, 256>>>(H);

    gemm_mma_kernel<<<(N_NODES + 127) / 128, 256>>>(H, b, out);
}